// round 2
// baseline (speedup 1.0000x reference)
#include <cuda_runtime.h>
#include <cuda_bf16.h>
#include <math.h>

// Problem dims
#define BB   64
#define SS   512
#define DD   768
#define WW   256
#define HH   384
#define FOURH 1536
#define CC   425
#define MM   (BB*SS)      // 32768 rows

// Recurrence config
#define NC     48          // CTAs per direction
#define CHUNK  8           // h-indices per CTA (48*8 = 384)
#define RROWS  32          // gate rows per CTA (4 gates * CHUNK)
#define RTH    128         // threads in recurrence kernel

// -------- scratch (device globals; no allocation allowed) --------
__device__ float g_x  [MM * DD];        // pooled input            [B*S, D]
__device__ float g_xpf[MM * FOURH];     // fwd input projections   [B*S, 4H]
__device__ float g_xpb[MM * FOURH];     // bwd input projections
__device__ float g_f1 [MM * 2 * HH];    // concat hidden states    [B*S, 2H]
__device__ float g_hbuf[2][HH * BB];    // h state, layout [dir][k*64 + b]
__device__ unsigned g_bar[2][SS];       // per-step barrier counters

// ---------------- init: zero state + barriers (every replay) ----------------
__global__ void init_kernel()
{
    int tid = threadIdx.x + blockIdx.x * blockDim.x;
    int nt  = blockDim.x * gridDim.x;
    float* hb = &g_hbuf[0][0];
    for (int i = tid; i < 2 * HH * BB; i += nt) hb[i] = 0.0f;
    unsigned* bp = &g_bar[0][0];
    for (int i = tid; i < 2 * SS; i += nt) bp[i] = 0u;
}

// ---------------- segment mean pool ----------------
__global__ void pool_kernel(const float* __restrict__ f0,
                            const int*   __restrict__ counts,
                            float*       __restrict__ xout)
{
    __shared__ int s_start[WW];
    __shared__ int s_cnt[WW];
    int b = blockIdx.x;
    int tid = threadIdx.x;
    if (tid == 0) {
        int run = 0;
        for (int j = 0; j < WW; ++j) {
            int c = counts[b * WW + j];
            s_start[j] = run; s_cnt[j] = c; run += c;
        }
    }
    __syncthreads();
    const float* fb = f0 + (size_t)b * SS * DD;
    float* xb = xout + (size_t)b * SS * DD;
    // pooled words [0, W)
    for (int idx = tid; idx < WW * DD; idx += blockDim.x) {
        int j = idx / DD, d = idx - j * DD;
        int st = s_start[j], c = s_cnt[j];
        float v = 0.0f;
        for (int p = 0; p < c; ++p) v += fb[(size_t)(st + p) * DD + d];
        xb[idx] = v / (float)c;
    }
    // tail [W, S): raw copy
    for (int idx = tid; idx < (SS - WW) * DD; idx += blockDim.x) {
        xb[WW * DD + idx] = fb[WW * DD + idx];
    }
}

// ---------------- generic SGEMM: C[M,N] = A[M,K] * Bw[N,K]^T + bias1 + bias2 ----------------
// 128x128 tiles, BK=8, 256 threads, 8x8 per-thread micro tile.
// M must be a multiple of 128, K a multiple of 8. N is guarded.
__global__ void __launch_bounds__(256)
sgemm_bias_kernel(const float* __restrict__ A, const float* __restrict__ Bw,
                  const float* __restrict__ bias1, const float* __restrict__ bias2,
                  float* __restrict__ C, int M, int N, int K)
{
    __shared__ float As[8][128];
    __shared__ float Bs[8][128];
    int tid = threadIdx.x;
    int bm = blockIdx.y, bn = blockIdx.x;

    int loadRow = tid >> 1;            // 0..127
    int loadCol = (tid & 1) * 4;       // 0 or 4
    const float* Aptr = A + (size_t)(bm * 128 + loadRow) * K + loadCol;
    int bRow = bn * 128 + loadRow;
    const float* Bptr = Bw + (size_t)bRow * K + loadCol;
    bool bValid = (bRow < N);

    int rowBase = (tid >> 4) * 8;      // 0..120
    int colBase = (tid & 15) * 8;      // 0..120

    float acc[8][8];
#pragma unroll
    for (int i = 0; i < 8; ++i)
#pragma unroll
        for (int j = 0; j < 8; ++j) acc[i][j] = 0.0f;

    for (int kt = 0; kt < K; kt += 8) {
        float4 av = *(const float4*)(Aptr + kt);
        float4 bv = bValid ? *(const float4*)(Bptr + kt) : make_float4(0.f, 0.f, 0.f, 0.f);
        As[loadCol + 0][loadRow] = av.x;
        As[loadCol + 1][loadRow] = av.y;
        As[loadCol + 2][loadRow] = av.z;
        As[loadCol + 3][loadRow] = av.w;
        Bs[loadCol + 0][loadRow] = bv.x;
        Bs[loadCol + 1][loadRow] = bv.y;
        Bs[loadCol + 2][loadRow] = bv.z;
        Bs[loadCol + 3][loadRow] = bv.w;
        __syncthreads();
#pragma unroll
        for (int kk = 0; kk < 8; ++kk) {
            float ar[8], br[8];
            *(float4*)&ar[0] = *(const float4*)&As[kk][rowBase];
            *(float4*)&ar[4] = *(const float4*)&As[kk][rowBase + 4];
            *(float4*)&br[0] = *(const float4*)&Bs[kk][colBase];
            *(float4*)&br[4] = *(const float4*)&Bs[kk][colBase + 4];
#pragma unroll
            for (int i = 0; i < 8; ++i)
#pragma unroll
                for (int j = 0; j < 8; ++j)
                    acc[i][j] = fmaf(ar[i], br[j], acc[i][j]);
        }
        __syncthreads();
    }

#pragma unroll
    for (int i = 0; i < 8; ++i) {
        int row = bm * 128 + rowBase + i;
        float* Crow = C + (size_t)row * N;
#pragma unroll
        for (int j = 0; j < 8; ++j) {
            int col = bn * 128 + colBase + j;
            if (col < N) {
                float bsum = bias1[col] + (bias2 ? bias2[col] : 0.0f);
                Crow[col] = acc[i][j] + bsum;
            }
        }
    }
}

// ---------------- persistent bidirectional LSTM recurrence ----------------
// 96 CTAs total: [0,48) forward, [48,96) backward. Each CTA owns CHUNK=8
// h-indices (32 gate rows). Whh slice cached in SMEM for all 512 steps.
// Full h (96KB) copied L2->SMEM each step via __ldcg (L1 bypass).
__global__ void __launch_bounds__(RTH, 1)
lstm_kernel(const float* __restrict__ Whh_f, const float* __restrict__ Whh_b)
{
    extern __shared__ float sm[];
    float* h_s     = sm;                         // [384*64]
    float* W_s     = h_s + HH * BB;              // [384*32]  layout [k][r]
    float* gates_s = W_s + HH * RROWS;           // [32*64]   layout [r][b]
    float* c_s     = gates_s + RROWS * BB;       // [8*64]    layout [j][b]

    int cta = blockIdx.x;
    int dir = (cta >= NC) ? 1 : 0;
    int ci  = cta - dir * NC;
    const float* Whh = dir ? Whh_b : Whh_f;
    const float* xp  = dir ? g_xpb : g_xpf;
    int n0  = ci * CHUNK;
    int tid = threadIdx.x;

    // cache Whh slice: W_s[k*32 + r] = Whh[(gi*H + n0 + j)*H + k], r = gi*8 + j
    for (int idx = tid; idx < RROWS * HH; idx += RTH) {
        int r = idx / HH, k = idx - r * HH;
        int gi = r >> 3, j = r & 7;
        W_s[k * RROWS + r] = Whh[(size_t)(gi * HH + n0 + j) * HH + k];
    }
    for (int idx = tid; idx < CHUNK * BB; idx += RTH) c_s[idx] = 0.0f;
    __syncthreads();

    int tb = tid & 15;      // 0..15 -> batch group
    int tr = tid >> 4;      // 0..7  -> row group
    int b0 = tb * 4;
    int r0 = tr * 4;
    float* hb = &g_hbuf[dir][0];

    for (int s = 0; s < SS; ++s) {
        int t = dir ? (SS - 1 - s) : s;

        // load full h state into SMEM (bypass L1: written by other SMs)
        {
            const float4* src = (const float4*)hb;
            float4* dst = (float4*)h_s;
#pragma unroll 4
            for (int idx = tid; idx < HH * BB / 4; idx += RTH)
                dst[idx] = __ldcg(src + idx);
        }
        __syncthreads();

        // accumulators init from precomputed input projections
        float acc[4][4];
#pragma unroll
        for (int ni = 0; ni < 4; ++ni) {
            int r = r0 + ni;
            int grow = (r >> 3) * HH + n0 + (r & 7);
#pragma unroll
            for (int mi = 0; mi < 4; ++mi)
                acc[mi][ni] = __ldg(&xp[((size_t)(b0 + mi) * SS + t) * FOURH + grow]);
        }

        // gates += h @ Whh^T  (per-thread 4x4 tile)
#pragma unroll 4
        for (int k = 0; k < HH; ++k) {
            float4 hv = *(const float4*)(h_s + k * BB + b0);
            float4 wv = *(const float4*)(W_s + k * RROWS + r0);
            acc[0][0] = fmaf(hv.x, wv.x, acc[0][0]);
            acc[1][0] = fmaf(hv.y, wv.x, acc[1][0]);
            acc[2][0] = fmaf(hv.z, wv.x, acc[2][0]);
            acc[3][0] = fmaf(hv.w, wv.x, acc[3][0]);
            acc[0][1] = fmaf(hv.x, wv.y, acc[0][1]);
            acc[1][1] = fmaf(hv.y, wv.y, acc[1][1]);
            acc[2][1] = fmaf(hv.z, wv.y, acc[2][1]);
            acc[3][1] = fmaf(hv.w, wv.y, acc[3][1]);
            acc[0][2] = fmaf(hv.x, wv.z, acc[0][2]);
            acc[1][2] = fmaf(hv.y, wv.z, acc[1][2]);
            acc[2][2] = fmaf(hv.z, wv.z, acc[2][2]);
            acc[3][2] = fmaf(hv.w, wv.z, acc[3][2]);
            acc[0][3] = fmaf(hv.x, wv.w, acc[0][3]);
            acc[1][3] = fmaf(hv.y, wv.w, acc[1][3]);
            acc[2][3] = fmaf(hv.z, wv.w, acc[2][3]);
            acc[3][3] = fmaf(hv.w, wv.w, acc[3][3]);
        }

        // stash gates to SMEM for the i/f/g/o regrouping
#pragma unroll
        for (int ni = 0; ni < 4; ++ni) {
            *(float4*)&gates_s[(r0 + ni) * BB + b0] =
                make_float4(acc[0][ni], acc[1][ni], acc[2][ni], acc[3][ni]);
        }
        __syncthreads();

        // LSTM cell update for this CTA's 8*64 cells
#pragma unroll
        for (int u = 0; u < 4; ++u) {
            int idx = tid + u * RTH;           // 0..511
            int j = idx >> 6, bidx = idx & 63;
            float ig = gates_s[(0 * CHUNK + j) * BB + bidx];
            float fg = gates_s[(1 * CHUNK + j) * BB + bidx];
            float gg = gates_s[(2 * CHUNK + j) * BB + bidx];
            float og = gates_s[(3 * CHUNK + j) * BB + bidx];
            float c  = c_s[idx];
            float si = 1.0f / (1.0f + expf(-ig));
            float sf = 1.0f / (1.0f + expf(-fg));
            float so = 1.0f / (1.0f + expf(-og));
            c = sf * c + si * tanhf(gg);
            float h = so * tanhf(c);
            c_s[idx] = c;
            __stcg(&hb[(n0 + j) * BB + bidx], h);
            g_f1[((size_t)bidx * SS + t) * (2 * HH) + dir * HH + n0 + j] = h;
        }

        // inter-CTA barrier (per direction, per-step counter slot)
        __threadfence();
        __syncthreads();
        if (tid == 0) {
            atomicAdd(&g_bar[dir][s], 1u);
            while (*(volatile unsigned*)&g_bar[dir][s] < (unsigned)NC) { }
        }
        __syncthreads();
    }
}

// ---------------- launcher ----------------
extern "C" void kernel_launch(void* const* d_in, const int* in_sizes, int n_in,
                              void* d_out, int out_size)
{
    const float* f0     = (const float*)d_in[0];
    const int*   counts = (const int*)  d_in[1];
    const float* Wih_f  = (const float*)d_in[2];
    const float* Whh_f  = (const float*)d_in[3];
    const float* bih_f  = (const float*)d_in[4];
    const float* bhh_f  = (const float*)d_in[5];
    const float* Wih_b  = (const float*)d_in[6];
    const float* Whh_b  = (const float*)d_in[7];
    const float* bih_b  = (const float*)d_in[8];
    const float* bhh_b  = (const float*)d_in[9];
    const float* Wlin   = (const float*)d_in[10];
    const float* blin   = (const float*)d_in[11];
    float* out = (float*)d_out;

    void* p;
    cudaGetSymbolAddress(&p, g_x);   float* gx   = (float*)p;
    cudaGetSymbolAddress(&p, g_xpf); float* gxpf = (float*)p;
    cudaGetSymbolAddress(&p, g_xpb); float* gxpb = (float*)p;
    cudaGetSymbolAddress(&p, g_f1);  float* gf1  = (float*)p;

    const int lstm_smem = (HH * BB + HH * RROWS + RROWS * BB + CHUNK * BB) * (int)sizeof(float);
    cudaFuncSetAttribute(lstm_kernel, cudaFuncAttributeMaxDynamicSharedMemorySize, lstm_smem);

    init_kernel<<<2, 256>>>();
    pool_kernel<<<BB, 256>>>(f0, counts, gx);

    dim3 gproj(FOURH / 128, MM / 128);   // 12 x 256
    sgemm_bias_kernel<<<gproj, 256>>>(gx, Wih_f, bih_f, bhh_f, gxpf, MM, FOURH, DD);
    sgemm_bias_kernel<<<gproj, 256>>>(gx, Wih_b, bih_b, bhh_b, gxpb, MM, FOURH, DD);

    lstm_kernel<<<2 * NC, RTH, lstm_smem>>>(Whh_f, Whh_b);

    dim3 gout((CC + 127) / 128, MM / 128);  // 4 x 256
    sgemm_bias_kernel<<<gout, 256>>>(gf1, Wlin, blin, nullptr, out, MM, CC, 2 * HH);
}

// round 3
// speedup vs baseline: 2.3126x; 2.3126x over previous
#include <cuda_runtime.h>
#include <cuda_bf16.h>
#include <math.h>
#include <stdint.h>

// Problem dims
#define BB   64
#define SS   512
#define DD   768
#define WW   256
#define HH   384
#define FOURH 1536
#define CC   425
#define K2H  768
#define MM   (BB*SS)      // 32768 rows

// Recurrence config
#define NC     48          // CTAs per direction
#define CHUNK  8           // h-indices per CTA
#define RROWS  32          // gate rows per CTA
#define RTH    128

// -------- scratch (device globals; no allocation allowed) --------
__device__ __nv_bfloat16 g_xhi[MM * DD];
__device__ __nv_bfloat16 g_xlo[MM * DD];
__device__ float g_xpf[MM * FOURH];
__device__ float g_xpb[MM * FOURH];
__device__ __nv_bfloat16 g_f1hi[MM * K2H];
__device__ __nv_bfloat16 g_f1lo[MM * K2H];
__device__ float g_hbuf[2][HH * BB];
__device__ unsigned g_bar[2][SS];
__device__ __nv_bfloat16 g_wihf_hi[FOURH * DD], g_wihf_lo[FOURH * DD];
__device__ __nv_bfloat16 g_wihb_hi[FOURH * DD], g_wihb_lo[FOURH * DD];
__device__ __nv_bfloat16 g_wlin_hi[CC * K2H],  g_wlin_lo[CC * K2H];

// ---------------- small helpers ----------------
__device__ __forceinline__ uint32_t smem_u32(const void* p) {
    uint32_t a;
    asm("{ .reg .u64 t; cvta.to.shared.u64 t, %1; cvt.u32.u64 %0, t; }"
        : "=r"(a) : "l"(p));
    return a;
}
__device__ __forceinline__ void cp16(uint32_t d, const void* s, bool v) {
    int sz = v ? 16 : 0;
    asm volatile("cp.async.cg.shared.global [%0], [%1], 16, %2;\n"
                 :: "r"(d), "l"(s), "r"(sz));
}
#define CP_COMMIT() asm volatile("cp.async.commit_group;\n")
#define CP_WAIT(n)  asm volatile("cp.async.wait_group %0;\n" :: "n"(n))

#define LDM4(r, addr) \
    asm volatile("ldmatrix.sync.aligned.m8n8.x4.shared.b16 {%0,%1,%2,%3}, [%4];" \
        : "=r"((r)[0]), "=r"((r)[1]), "=r"((r)[2]), "=r"((r)[3]) : "r"(addr))

#define MMA(d, a, b0, b1) \
    asm volatile("mma.sync.aligned.m16n8k16.row.col.f32.bf16.bf16.f32 " \
        "{%0,%1,%2,%3},{%4,%5,%6,%7},{%8,%9},{%0,%1,%2,%3};" \
        : "+f"((d)[0]), "+f"((d)[1]), "+f"((d)[2]), "+f"((d)[3]) \
        : "r"((a)[0]), "r"((a)[1]), "r"((a)[2]), "r"((a)[3]), "r"(b0), "r"(b1))

// ---------------- init: zero state + barriers (every replay) ----------------
__global__ void init_kernel()
{
    int tid = threadIdx.x + blockIdx.x * blockDim.x;
    int nt  = blockDim.x * gridDim.x;
    float* hb = &g_hbuf[0][0];
    for (int i = tid; i < 2 * HH * BB; i += nt) hb[i] = 0.0f;
    unsigned* bp = &g_bar[0][0];
    for (int i = tid; i < 2 * SS; i += nt) bp[i] = 0u;
}

// ---------------- fp32 -> (hi, lo) bf16 split ----------------
__global__ void cvt_kernel(const float* __restrict__ in,
                           __nv_bfloat16* __restrict__ hi,
                           __nv_bfloat16* __restrict__ lo, int n)
{
    int i = blockIdx.x * blockDim.x + threadIdx.x;
    if (i < n) {
        float v = in[i];
        __nv_bfloat16 h = __float2bfloat16(v);
        hi[i] = h;
        lo[i] = __float2bfloat16(v - __bfloat162float(h));
    }
}

// ---------------- segment mean pool (writes split bf16) ----------------
__global__ void pool_kernel(const float* __restrict__ f0,
                            const int*   __restrict__ counts,
                            __nv_bfloat16* __restrict__ xhi,
                            __nv_bfloat16* __restrict__ xlo)
{
    __shared__ int s_start[WW];
    __shared__ int s_cnt[WW];
    int b = blockIdx.x;
    int tid = threadIdx.x;
    if (tid == 0) {
        int run = 0;
        for (int j = 0; j < WW; ++j) {
            int c = counts[b * WW + j];
            s_start[j] = run; s_cnt[j] = c; run += c;
        }
    }
    __syncthreads();
    const float* fb = f0 + (size_t)b * SS * DD;
    __nv_bfloat16* xh = xhi + (size_t)b * SS * DD;
    __nv_bfloat16* xl = xlo + (size_t)b * SS * DD;
    for (int idx = tid; idx < WW * DD; idx += blockDim.x) {
        int j = idx / DD, d = idx - j * DD;
        int st = s_start[j], c = s_cnt[j];
        float v = 0.0f;
        for (int p = 0; p < c; ++p) v += fb[(size_t)(st + p) * DD + d];
        v /= (float)c;
        __nv_bfloat16 h = __float2bfloat16(v);
        xh[idx] = h;
        xl[idx] = __float2bfloat16(v - __bfloat162float(h));
    }
    for (int idx = tid; idx < (SS - WW) * DD; idx += blockDim.x) {
        float v = fb[WW * DD + idx];
        __nv_bfloat16 h = __float2bfloat16(v);
        xh[WW * DD + idx] = h;
        xl[WW * DD + idx] = __float2bfloat16(v - __bfloat162float(h));
    }
}

// ---------------- split-bf16 tensor-core GEMM ----------------
// C[M,N] = (Ahi+Alo)[M,K] * (Bhi+Blo)[N,K]^T + bias1 + bias2
// 3-term split: Ahi*Bhi + Ahi*Blo + Alo*Bhi (fp32 accumulate)
// 128x128 tile, BK=32, 256 threads (8 warps, 2x4 grid of 64x32 warp tiles).
// SMEM rows padded to 80B -> conflict-free ldmatrix. Double buffered cp.async.
#define ARRB  (128 * 80)
#define STGB  (4 * ARRB)

__global__ void __launch_bounds__(256, 1)
gemm3_kernel(const __nv_bfloat16* __restrict__ Ahi, const __nv_bfloat16* __restrict__ Alo,
             const __nv_bfloat16* __restrict__ Bhi, const __nv_bfloat16* __restrict__ Blo,
             const float* __restrict__ bias1, const float* __restrict__ bias2,
             float* __restrict__ C, int N, int K)
{
    extern __shared__ char smem[];
    uint32_t sb = smem_u32(smem);
    int tid = threadIdx.x, lane = tid & 31, wid = tid >> 5;
    int wm = wid >> 2, wn = wid & 3;
    int bm = blockIdx.y, bn = blockIdx.x;

    // cp.async load mapping: 2 threads per row, 2 chunks (16B) each per array
    int lr = tid >> 1;
    int lc = (tid & 1) * 2;
    int arow = bm * 128 + lr;
    int brow = bn * 128 + lr;
    bool bv  = brow < N;
    const __nv_bfloat16* pAh = Ahi + (size_t)arow * K;
    const __nv_bfloat16* pAl = Alo + (size_t)arow * K;
    const __nv_bfloat16* pBh = Bhi + (size_t)(bv ? brow : 0) * K;
    const __nv_bfloat16* pBl = Blo + (size_t)(bv ? brow : 0) * K;
    uint32_t sd = sb + lr * 80 + lc * 16;

    float acc[4][4][4];
#pragma unroll
    for (int a = 0; a < 4; ++a)
#pragma unroll
        for (int b = 0; b < 4; ++b)
#pragma unroll
            for (int c = 0; c < 4; ++c) acc[a][b][c] = 0.0f;

    int KT = K >> 5;

    // prologue: stage 0
    {
        uint32_t d = sd;
#pragma unroll
        for (int cc = 0; cc < 2; ++cc) {
            cp16(d + cc * 16 + 0 * ARRB, pAh + (lc + cc) * 8, true);
            cp16(d + cc * 16 + 1 * ARRB, pAl + (lc + cc) * 8, true);
            cp16(d + cc * 16 + 2 * ARRB, pBh + (lc + cc) * 8, bv);
            cp16(d + cc * 16 + 3 * ARRB, pBl + (lc + cc) * 8, bv);
        }
        CP_COMMIT();
    }

    int la  = lane & 15, lc4 = lane >> 4;
    int lb  = (lane & 7) + ((lane & 16) >> 1);
    int lbc = (lane >> 3) & 1;

    for (int i = 0; i < KT; ++i) {
        CP_WAIT(0);
        __syncthreads();
        if (i + 1 < KT) {
            int ko = (i + 1) << 5;
            uint32_t d = sd + ((i + 1) & 1) * STGB;
#pragma unroll
            for (int cc = 0; cc < 2; ++cc) {
                cp16(d + cc * 16 + 0 * ARRB, pAh + ko + (lc + cc) * 8, true);
                cp16(d + cc * 16 + 1 * ARRB, pAl + ko + (lc + cc) * 8, true);
                cp16(d + cc * 16 + 2 * ARRB, pBh + ko + (lc + cc) * 8, bv);
                cp16(d + cc * 16 + 3 * ARRB, pBl + ko + (lc + cc) * 8, bv);
            }
            CP_COMMIT();
        }
        uint32_t st = sb + (i & 1) * STGB;
#pragma unroll
        for (int kh = 0; kh < 2; ++kh) {
            uint32_t aaddr = st + (wm * 64 + la) * 80 + (kh * 2 + lc4) * 16;
            uint32_t ah[4][4], al[4][4];
#pragma unroll
            for (int mt = 0; mt < 4; ++mt) {
                LDM4(ah[mt], aaddr + mt * 1280);
                LDM4(al[mt], aaddr + mt * 1280 + ARRB);
            }
            uint32_t bbase = st + 2 * ARRB + (wn * 32 + lb) * 80 + (kh * 2 + lbc) * 16;
#pragma unroll
            for (int ntp = 0; ntp < 2; ++ntp) {
                uint32_t bh[4], bl[4];
                LDM4(bh, bbase + ntp * 1280);
                LDM4(bl, bbase + ntp * 1280 + ARRB);
#pragma unroll
                for (int mt = 0; mt < 4; ++mt) {
                    MMA(acc[mt][2 * ntp + 0], ah[mt], bh[0], bh[1]);
                    MMA(acc[mt][2 * ntp + 0], ah[mt], bl[0], bl[1]);
                    MMA(acc[mt][2 * ntp + 0], al[mt], bh[0], bh[1]);
                    MMA(acc[mt][2 * ntp + 1], ah[mt], bh[2], bh[3]);
                    MMA(acc[mt][2 * ntp + 1], ah[mt], bl[2], bl[3]);
                    MMA(acc[mt][2 * ntp + 1], al[mt], bh[2], bh[3]);
                }
            }
        }
        __syncthreads();
    }

    // epilogue
#pragma unroll
    for (int mt = 0; mt < 4; ++mt) {
        int m0 = bm * 128 + wm * 64 + mt * 16 + (lane >> 2);
#pragma unroll
        for (int nt = 0; nt < 4; ++nt) {
            int n0 = bn * 128 + wn * 32 + nt * 8 + (lane & 3) * 2;
            float* a = acc[mt][nt];
            if (n0 < N) {
                float bs = bias1[n0] + (bias2 ? bias2[n0] : 0.0f);
                C[(size_t)m0 * N + n0]       = a[0] + bs;
                C[(size_t)(m0 + 8) * N + n0] = a[2] + bs;
            }
            if (n0 + 1 < N) {
                float bs = bias1[n0 + 1] + (bias2 ? bias2[n0 + 1] : 0.0f);
                C[(size_t)m0 * N + n0 + 1]       = a[1] + bs;
                C[(size_t)(m0 + 8) * N + n0 + 1] = a[3] + bs;
            }
        }
    }
}

// ---------------- persistent bidirectional LSTM recurrence ----------------
__global__ void __launch_bounds__(RTH, 1)
lstm_kernel(const float* __restrict__ Whh_f, const float* __restrict__ Whh_b)
{
    extern __shared__ float sm[];
    float* h_s     = sm;                         // [384*64]
    float* W_s     = h_s + HH * BB;              // [384*32]  layout [k][r]
    float* gates_s = W_s + HH * RROWS;           // [32*64]   layout [r][b]
    float* c_s     = gates_s + RROWS * BB;       // [8*64]
    uint32_t h_s32 = smem_u32(h_s);

    int cta = blockIdx.x;
    int dir = (cta >= NC) ? 1 : 0;
    int ci  = cta - dir * NC;
    const float* Whh = dir ? Whh_b : Whh_f;
    const float* xp  = dir ? g_xpb : g_xpf;
    int n0  = ci * CHUNK;
    int tid = threadIdx.x;

    for (int idx = tid; idx < RROWS * HH; idx += RTH) {
        int r = idx / HH, k = idx - r * HH;
        int gi = r >> 3, j = r & 7;
        W_s[k * RROWS + r] = Whh[(size_t)(gi * HH + n0 + j) * HH + k];
    }
    for (int idx = tid; idx < CHUNK * BB; idx += RTH) c_s[idx] = 0.0f;
    __syncthreads();

    int tb = tid & 15, tr = tid >> 4;
    int b0 = tb * 4, r0 = tr * 4;
    int gi = tr >> 1;                // gate index for this thread's rows
    int jb = (tr & 1) * 4;           // j base
    float* hb = &g_hbuf[dir][0];
    const char* hbc = (const char*)hb;

    for (int s = 0; s < SS; ++s) {
        int t = dir ? (SS - 1 - s) : s;

        // issue h copy (96KB) in 4 chunks of 24KB via cp.async (L2 path)
#pragma unroll
        for (int q = 0; q < 4; ++q) {
#pragma unroll
            for (int i = 0; i < 12; ++i) {
                int off = q * 24576 + (tid + i * RTH) * 16;
                cp16(h_s32 + off, hbc + off, true);
            }
            CP_COMMIT();
        }

        // xp prefetch (4 x LDG.128), overlapped with chunk 0 arrival
        float acc[4][4];
        {
            int colb = gi * HH + n0 + jb;
#pragma unroll
            for (int mi = 0; mi < 4; ++mi) {
                float4 xv = *(const float4*)&xp[((size_t)(b0 + mi) * SS + t) * FOURH + colb];
                acc[mi][0] = xv.x; acc[mi][1] = xv.y; acc[mi][2] = xv.z; acc[mi][3] = xv.w;
            }
        }

        // chunked compute, overlapping later chunk copies with FMA
#pragma unroll
        for (int q = 0; q < 4; ++q) {
            if      (q == 0) CP_WAIT(3);
            else if (q == 1) CP_WAIT(2);
            else if (q == 2) CP_WAIT(1);
            else             CP_WAIT(0);
            __syncthreads();
            int k0 = q * 96, k1 = k0 + 96;
#pragma unroll 4
            for (int k = k0; k < k1; ++k) {
                float4 hv = *(const float4*)(h_s + k * BB + b0);
                float4 wv = *(const float4*)(W_s + k * RROWS + r0);
                acc[0][0] = fmaf(hv.x, wv.x, acc[0][0]);
                acc[1][0] = fmaf(hv.y, wv.x, acc[1][0]);
                acc[2][0] = fmaf(hv.z, wv.x, acc[2][0]);
                acc[3][0] = fmaf(hv.w, wv.x, acc[3][0]);
                acc[0][1] = fmaf(hv.x, wv.y, acc[0][1]);
                acc[1][1] = fmaf(hv.y, wv.y, acc[1][1]);
                acc[2][1] = fmaf(hv.z, wv.y, acc[2][1]);
                acc[3][1] = fmaf(hv.w, wv.y, acc[3][1]);
                acc[0][2] = fmaf(hv.x, wv.z, acc[0][2]);
                acc[1][2] = fmaf(hv.y, wv.z, acc[1][2]);
                acc[2][2] = fmaf(hv.z, wv.z, acc[2][2]);
                acc[3][2] = fmaf(hv.w, wv.z, acc[3][2]);
                acc[0][3] = fmaf(hv.x, wv.w, acc[0][3]);
                acc[1][3] = fmaf(hv.y, wv.w, acc[1][3]);
                acc[2][3] = fmaf(hv.z, wv.w, acc[2][3]);
                acc[3][3] = fmaf(hv.w, wv.w, acc[3][3]);
            }
        }

#pragma unroll
        for (int ni = 0; ni < 4; ++ni) {
            *(float4*)&gates_s[(r0 + ni) * BB + b0] =
                make_float4(acc[0][ni], acc[1][ni], acc[2][ni], acc[3][ni]);
        }
        __syncthreads();

#pragma unroll
        for (int u = 0; u < 4; ++u) {
            int idx = tid + u * RTH;
            int j = idx >> 6, b = idx & 63;
            float ig = gates_s[(0 * CHUNK + j) * BB + b];
            float fg = gates_s[(1 * CHUNK + j) * BB + b];
            float gg = gates_s[(2 * CHUNK + j) * BB + b];
            float og = gates_s[(3 * CHUNK + j) * BB + b];
            float c  = c_s[idx];
            float si = 1.0f / (1.0f + expf(-ig));
            float sf = 1.0f / (1.0f + expf(-fg));
            float so = 1.0f / (1.0f + expf(-og));
            c = sf * c + si * tanhf(gg);
            float h = so * tanhf(c);
            c_s[idx] = c;
            __stcg(&hb[(n0 + j) * BB + b], h);
            __nv_bfloat16 hh = __float2bfloat16(h);
            size_t fo = ((size_t)b * SS + t) * K2H + dir * HH + n0 + j;
            g_f1hi[fo] = hh;
            g_f1lo[fo] = __float2bfloat16(h - __bfloat162float(hh));
        }

        __threadfence();
        __syncthreads();
        if (tid == 0) {
            atomicAdd(&g_bar[dir][s], 1u);
            while (*(volatile unsigned*)&g_bar[dir][s] < (unsigned)NC) { }
        }
        __syncthreads();
    }
}

// ---------------- launcher ----------------
extern "C" void kernel_launch(void* const* d_in, const int* in_sizes, int n_in,
                              void* d_out, int out_size)
{
    const float* f0     = (const float*)d_in[0];
    const int*   counts = (const int*)  d_in[1];
    const float* Wih_f  = (const float*)d_in[2];
    const float* Whh_f  = (const float*)d_in[3];
    const float* bih_f  = (const float*)d_in[4];
    const float* bhh_f  = (const float*)d_in[5];
    const float* Wih_b  = (const float*)d_in[6];
    const float* Whh_b  = (const float*)d_in[7];
    const float* bih_b  = (const float*)d_in[8];
    const float* bhh_b  = (const float*)d_in[9];
    const float* Wlin   = (const float*)d_in[10];
    const float* blin   = (const float*)d_in[11];
    float* out = (float*)d_out;

    void* p;
    cudaGetSymbolAddress(&p, g_xhi);     __nv_bfloat16* xhi = (__nv_bfloat16*)p;
    cudaGetSymbolAddress(&p, g_xlo);     __nv_bfloat16* xlo = (__nv_bfloat16*)p;
    cudaGetSymbolAddress(&p, g_xpf);     float* gxpf = (float*)p;
    cudaGetSymbolAddress(&p, g_xpb);     float* gxpb = (float*)p;
    cudaGetSymbolAddress(&p, g_f1hi);    __nv_bfloat16* f1hi = (__nv_bfloat16*)p;
    cudaGetSymbolAddress(&p, g_f1lo);    __nv_bfloat16* f1lo = (__nv_bfloat16*)p;
    cudaGetSymbolAddress(&p, g_wihf_hi); __nv_bfloat16* wfh = (__nv_bfloat16*)p;
    cudaGetSymbolAddress(&p, g_wihf_lo); __nv_bfloat16* wfl = (__nv_bfloat16*)p;
    cudaGetSymbolAddress(&p, g_wihb_hi); __nv_bfloat16* wbh = (__nv_bfloat16*)p;
    cudaGetSymbolAddress(&p, g_wihb_lo); __nv_bfloat16* wbl = (__nv_bfloat16*)p;
    cudaGetSymbolAddress(&p, g_wlin_hi); __nv_bfloat16* wlh = (__nv_bfloat16*)p;
    cudaGetSymbolAddress(&p, g_wlin_lo); __nv_bfloat16* wll = (__nv_bfloat16*)p;

    const int lstm_smem = (HH * BB + HH * RROWS + RROWS * BB + CHUNK * BB) * (int)sizeof(float);
    cudaFuncSetAttribute(lstm_kernel, cudaFuncAttributeMaxDynamicSharedMemorySize, lstm_smem);
    cudaFuncSetAttribute(gemm3_kernel, cudaFuncAttributeMaxDynamicSharedMemorySize, 2 * STGB);

    init_kernel<<<2, 256>>>();
    pool_kernel<<<BB, 256>>>(f0, counts, xhi, xlo);

    int nw = FOURH * DD;
    cvt_kernel<<<(nw + 255) / 256, 256>>>(Wih_f, wfh, wfl, nw);
    cvt_kernel<<<(nw + 255) / 256, 256>>>(Wih_b, wbh, wbl, nw);
    int nl = CC * K2H;
    cvt_kernel<<<(nl + 255) / 256, 256>>>(Wlin, wlh, wll, nl);

    dim3 gproj(FOURH / 128, MM / 128);   // 12 x 256
    gemm3_kernel<<<gproj, 256, 2 * STGB>>>(xhi, xlo, wfh, wfl, bih_f, bhh_f, gxpf, FOURH, DD);
    gemm3_kernel<<<gproj, 256, 2 * STGB>>>(xhi, xlo, wbh, wbl, bih_b, bhh_b, gxpb, FOURH, DD);

    lstm_kernel<<<2 * NC, RTH, lstm_smem>>>(Whh_f, Whh_b);

    dim3 gout((CC + 127) / 128, MM / 128);  // 4 x 256
    gemm3_kernel<<<gout, 256, 2 * STGB>>>(f1hi, f1lo, wlh, wll, blin, nullptr, out, CC, K2H);
}